// round 1
// baseline (speedup 1.0000x reference)
#include <cuda_runtime.h>
#include <cuda_bf16.h>
#include <cstdint>

// Problem constants (fixed by the reference)
#define Nn 4096
#define Mm 4096
#define Dd 1024

// GEMM tiling
#define BM 128
#define BN 128
#define BK 32
#define SKEW 8
#define BKP (BK + SKEW)          // 40 bf16 per smem row (80B, conflict-free for ldmatrix)
#define NSPLIT 8
#define NCHUNK (Nn / NSPLIT)     // 512
#define NT (NCHUNK / BN)         // 4 n-tiles per block
#define KT (Dd / BK)             // 32 k-tiles

// -------- scratch (device globals; no allocations allowed) --------
__device__ __align__(256) __nv_bfloat16 g_zb[Nn * Dd];   // z in bf16
__device__ __align__(256) __nv_bfloat16 g_eb[Mm * Dd];   // e in bf16
__device__ __align__(256) float g_zsq[Nn];               // ||z_n||^2 (fp32)
__device__ __align__(256) float g_esq[Mm];               // ||e_m||^2 (fp32)
__device__ __align__(256) float g_partial[NSPLIT * Mm];  // per-split row mins of (zsq - 2*cross)

// ================= kernel 1: convert + squared norms =================
__global__ void convert_kernel(const float* __restrict__ z, const float* __restrict__ e) {
    const int row = blockIdx.x;     // 0..8191 (z rows then e rows)
    const int t = threadIdx.x;      // 256 threads, 4 floats each
    const float* src;
    __nv_bfloat16* dst;
    float* sqout;
    if (row < Nn) {
        src = z + (size_t)row * Dd;
        dst = g_zb + (size_t)row * Dd;
        sqout = &g_zsq[row];
    } else {
        const int r = row - Nn;
        src = e + (size_t)r * Dd;
        dst = g_eb + (size_t)r * Dd;
        sqout = &g_esq[r];
    }
    float4 v = reinterpret_cast<const float4*>(src)[t];
    __nv_bfloat162 p0 = __floats2bfloat162_rn(v.x, v.y);
    __nv_bfloat162 p1 = __floats2bfloat162_rn(v.z, v.w);
    uint2 w;
    w.x = *reinterpret_cast<unsigned*>(&p0);
    w.y = *reinterpret_cast<unsigned*>(&p1);
    reinterpret_cast<uint2*>(dst)[t] = w;

    float s = v.x * v.x + v.y * v.y + v.z * v.z + v.w * v.w;
#pragma unroll
    for (int off = 16; off; off >>= 1) s += __shfl_xor_sync(0xffffffffu, s, off);
    __shared__ float ws[8];
    if ((t & 31) == 0) ws[t >> 5] = s;
    __syncthreads();
    if (t == 0) {
        float tot = 0.f;
#pragma unroll
        for (int i = 0; i < 8; i++) tot += ws[i];
        *sqout = tot;
    }
}

// ================= PTX helpers =================
__device__ __forceinline__ void cp_async16(uint32_t saddr, const void* gptr) {
    asm volatile("cp.async.cg.shared.global [%0], [%1], 16;\n" ::"r"(saddr), "l"(gptr));
}
__device__ __forceinline__ void cp_commit() { asm volatile("cp.async.commit_group;\n"); }
template <int NW>
__device__ __forceinline__ void cp_wait() { asm volatile("cp.async.wait_group %0;\n" ::"n"(NW)); }

__device__ __forceinline__ void ldsm4(uint32_t& r0, uint32_t& r1, uint32_t& r2, uint32_t& r3,
                                      uint32_t saddr) {
    asm volatile("ldmatrix.sync.aligned.m8n8.x4.shared.b16 {%0,%1,%2,%3}, [%4];\n"
                 : "=r"(r0), "=r"(r1), "=r"(r2), "=r"(r3)
                 : "r"(saddr));
}
__device__ __forceinline__ void mma16816(float* c, const uint32_t* a, uint32_t b0, uint32_t b1) {
    asm volatile(
        "mma.sync.aligned.m16n8k16.row.col.f32.bf16.bf16.f32 "
        "{%0,%1,%2,%3}, {%4,%5,%6,%7}, {%8,%9}, {%0,%1,%2,%3};\n"
        : "+f"(c[0]), "+f"(c[1]), "+f"(c[2]), "+f"(c[3])
        : "r"(a[0]), "r"(a[1]), "r"(a[2]), "r"(a[3]), "r"(b0), "r"(b1));
}

// ================= kernel 2: fused GEMM + row-min =================
// Block: computes rows [m0, m0+128) of e against n-strip [split*512, +512) of z.
// acc[m][n] = e_m . z_n ; epilogue folds v = zsq[n] - 2*acc, keeps per-m running min
// in registers across the strip's 4 n-tiles; writes one partial min per (m, split).
__global__ __launch_bounds__(256, 2) void gemm_min_kernel() {
    __shared__ __nv_bfloat16 sA[2][BM][BKP];   // e tile (double buffered)
    __shared__ __nv_bfloat16 sB[2][BN][BKP];   // z tile
    __shared__ float srm[2][BM];

    const int mblk = blockIdx.x;
    const int split = blockIdx.y;
    const int m0 = mblk * BM;
    const int nbase = split * NCHUNK;
    const int tid = threadIdx.x;
    const int lane = tid & 31;
    const int warp = tid >> 5;
    const int wm = warp >> 1;   // 0..3 : 32-row group
    const int wn = warp & 1;    // 0..1 : 64-col group

    // global->smem load mapping: thread -> (row, two consecutive 16B chunks)
    const int lrow = tid >> 1;
    const int lseg = (tid & 1) * 2;   // 16B-chunk base index (0 or 2)

    const uint32_t sA0 = (uint32_t)__cvta_generic_to_shared(&sA[0][0][0]);
    const uint32_t sB0 = (uint32_t)__cvta_generic_to_shared(&sB[0][0][0]);

    const float INF = __int_as_float(0x7f800000);
    float rm0 = INF, rm1 = INF, rm2 = INF, rm3 = INF;  // rows: wm*32 + {r, r+8, 16+r, 24+r}

    // ldmatrix per-lane offsets
    const int ldrow = lane & 15;
    const int ldcol = (lane >> 4) * 8;

    for (int nt = 0; nt < NT; nt++) {
        const int n0 = nbase + nt * BN;
        float acc[2][8][4];
#pragma unroll
        for (int mi = 0; mi < 2; mi++)
#pragma unroll
            for (int g = 0; g < 8; g++)
#pragma unroll
                for (int j = 0; j < 4; j++) acc[mi][g][j] = 0.f;

        // prefetch k-tile 0 into buffer 0
        {
            const __nv_bfloat16* gA = g_eb + (size_t)(m0 + lrow) * Dd + lseg * 8;
            const __nv_bfloat16* gB = g_zb + (size_t)(n0 + lrow) * Dd + lseg * 8;
            const uint32_t dA = sA0 + (uint32_t)(lrow * BKP + lseg * 8) * 2;
            const uint32_t dB = sB0 + (uint32_t)(lrow * BKP + lseg * 8) * 2;
            cp_async16(dA, gA);
            cp_async16(dA + 16, gA + 8);
            cp_async16(dB, gB);
            cp_async16(dB + 16, gB + 8);
            cp_commit();
        }

        for (int kt = 0; kt < KT; kt++) {
            const int buf = kt & 1;
            if (kt + 1 < KT) {
                const int nb = (kt + 1) & 1;
                const int k0 = (kt + 1) * BK;
                const __nv_bfloat16* gA = g_eb + (size_t)(m0 + lrow) * Dd + k0 + lseg * 8;
                const __nv_bfloat16* gB = g_zb + (size_t)(n0 + lrow) * Dd + k0 + lseg * 8;
                const uint32_t dA = sA0 + (uint32_t)(nb * BM * BKP + lrow * BKP + lseg * 8) * 2;
                const uint32_t dB = sB0 + (uint32_t)(nb * BN * BKP + lrow * BKP + lseg * 8) * 2;
                cp_async16(dA, gA);
                cp_async16(dA + 16, gA + 8);
                cp_async16(dB, gB);
                cp_async16(dB + 16, gB + 8);
                cp_commit();
                cp_wait<1>();
            } else {
                cp_wait<0>();
            }
            __syncthreads();

#pragma unroll
            for (int ks = 0; ks < BK; ks += 16) {
                uint32_t a[2][4];
#pragma unroll
                for (int mi = 0; mi < 2; mi++) {
                    const uint32_t addr =
                        sA0 + (uint32_t)(buf * BM * BKP + (wm * 32 + mi * 16 + ldrow) * BKP +
                                         ks + ldcol) * 2;
                    ldsm4(a[mi][0], a[mi][1], a[mi][2], a[mi][3], addr);
                }
#pragma unroll
                for (int g = 0; g < 4; g++) {
                    uint32_t b0, b1, b2, b3;
                    const uint32_t addr =
                        sB0 + (uint32_t)(buf * BN * BKP + (wn * 64 + g * 16 + ldrow) * BKP +
                                         ks + ldcol) * 2;
                    ldsm4(b0, b1, b2, b3, addr);
#pragma unroll
                    for (int mi = 0; mi < 2; mi++) {
                        mma16816(acc[mi][2 * g], a[mi], b0, b2);
                        mma16816(acc[mi][2 * g + 1], a[mi], b1, b3);
                    }
                }
            }
            __syncthreads();
        }

        // epilogue: v = zsq[n] - 2*acc ; fold into running row mins
        const int colbase = n0 + wn * 64 + (lane & 3) * 2;
#pragma unroll
        for (int g = 0; g < 8; g++) {
            const int col = colbase + g * 8;
            const float zs0 = g_zsq[col];
            const float zs1 = g_zsq[col + 1];
            {
                const float v0 = fminf(fmaf(-2.f, acc[0][g][0], zs0), fmaf(-2.f, acc[0][g][1], zs1));
                const float v1 = fminf(fmaf(-2.f, acc[0][g][2], zs0), fmaf(-2.f, acc[0][g][3], zs1));
                rm0 = fminf(rm0, v0);
                rm1 = fminf(rm1, v1);
            }
            {
                const float v0 = fminf(fmaf(-2.f, acc[1][g][0], zs0), fmaf(-2.f, acc[1][g][1], zs1));
                const float v1 = fminf(fmaf(-2.f, acc[1][g][2], zs0), fmaf(-2.f, acc[1][g][3], zs1));
                rm2 = fminf(rm2, v0);
                rm3 = fminf(rm3, v1);
            }
        }
    }

    // reduce across the 4 lanes of each row quad
#pragma unroll
    for (int off = 1; off <= 2; off <<= 1) {
        rm0 = fminf(rm0, __shfl_xor_sync(0xffffffffu, rm0, off));
        rm1 = fminf(rm1, __shfl_xor_sync(0xffffffffu, rm1, off));
        rm2 = fminf(rm2, __shfl_xor_sync(0xffffffffu, rm2, off));
        rm3 = fminf(rm3, __shfl_xor_sync(0xffffffffu, rm3, off));
    }
    if ((lane & 3) == 0) {
        const int r = lane >> 2;
        srm[wn][wm * 32 + r] = rm0;
        srm[wn][wm * 32 + r + 8] = rm1;
        srm[wn][wm * 32 + 16 + r] = rm2;
        srm[wn][wm * 32 + 24 + r] = rm3;
    }
    __syncthreads();
    if (tid < BM) {
        g_partial[split * Mm + m0 + tid] = fminf(srm[0][tid], srm[1][tid]);
    }
}

// ================= kernel 3: finalize (min over splits, + ||e||^2, mean) =================
__global__ void finalize_kernel(float* __restrict__ out) {
    const int t = threadIdx.x;  // 256
    float s = 0.f;
    for (int m = t; m < Mm; m += 256) {
        float mn = g_partial[m];
#pragma unroll
        for (int sp = 1; sp < NSPLIT; sp++) mn = fminf(mn, g_partial[sp * Mm + m]);
        s += mn + g_esq[m];
    }
#pragma unroll
    for (int off = 16; off; off >>= 1) s += __shfl_xor_sync(0xffffffffu, s, off);
    __shared__ float ws[8];
    if ((t & 31) == 0) ws[t >> 5] = s;
    __syncthreads();
    if (t == 0) {
        float tot = 0.f;
#pragma unroll
        for (int i = 0; i < 8; i++) tot += ws[i];
        out[0] = tot / (float)Mm;
    }
}

// ================= entry point =================
extern "C" void kernel_launch(void* const* d_in, const int* in_sizes, int n_in,
                              void* d_out, int out_size) {
    const float* z = (const float*)d_in[0];  // [4096, 1024]
    const float* e = (const float*)d_in[1];  // [4096, 1024]
    float* out = (float*)d_out;              // [1]

    convert_kernel<<<Nn + Mm, 256>>>(z, e);
    dim3 grid(Mm / BM, NSPLIT);
    gemm_min_kernel<<<grid, 256>>>();
    finalize_kernel<<<1, 256>>>(out);
}